// round 4
// baseline (speedup 1.0000x reference)
#include <cuda_runtime.h>
#include <cstddef>

#define NN 100000
#define NE 3200000
#define FIN 512
#define HID 64
#define NC  64
#define KHOPS 20

typedef unsigned long long ull;

// ---------------- scratch (device globals; no allocation allowed) ------------
__device__ float g_h[(size_t)NN * HID];      // MLP hidden
__device__ float g_xA[(size_t)NN * NC];      // ping
__device__ float g_xB[(size_t)NN * NC];      // pong
__device__ int   g_counts[NN];
__device__ int   g_rowptr[NN + 1];
__device__ int   g_widx[NN];
__device__ int2  g_edges[NE];                // (sender, weight-bits) grouped by receiver

// ---------------- packed f32x2 helpers (Blackwell FFMA2 path) ----------------
__device__ __forceinline__ ull pack2(float x, float y) {
    ull r; asm("mov.b64 %0, {%1, %2};" : "=l"(r) : "f"(x), "f"(y)); return r;
}
__device__ __forceinline__ void fma2(ull& d, ull a, ull b) {
    asm("fma.rn.f32x2 %0, %1, %2, %0;" : "+l"(d) : "l"(a), "l"(b));
}
__device__ __forceinline__ float2 unpack2(ull v) {
    float2 r; asm("mov.b64 {%0, %1}, %2;" : "=f"(r.x), "=f"(r.y) : "l"(v)); return r;
}

// ---------------- CSR build --------------------------------------------------
__global__ void k_zero_counts() {
    int i = blockIdx.x * blockDim.x + threadIdx.x;
    if (i < NN) g_counts[i] = 0;
}

__global__ void k_hist(const int* __restrict__ rcv) {
    int e4 = blockIdx.x * blockDim.x + threadIdx.x;    // NE/4 threads
    if (e4 * 4 >= NE) return;
    int4 r = ((const int4*)rcv)[e4];
    atomicAdd(&g_counts[r.x], 1);
    atomicAdd(&g_counts[r.y], 1);
    atomicAdd(&g_counts[r.z], 1);
    atomicAdd(&g_counts[r.w], 1);
}

__global__ void k_scan() {
    __shared__ int sm[1024];
    const int t = threadIdx.x;
    const int CH = (NN + 1023) / 1024;             // 98
    int beg = t * CH;
    int end = beg + CH; if (end > NN) end = NN;
    if (beg > NN) beg = NN;
    int s = 0;
    for (int i = beg; i < end; ++i) s += g_counts[i];
    sm[t] = s;
    __syncthreads();
    for (int d = 1; d < 1024; d <<= 1) {
        int add = (t >= d) ? sm[t - d] : 0;
        __syncthreads();
        sm[t] += add;
        __syncthreads();
    }
    int off = (t == 0) ? 0 : sm[t - 1];
    for (int i = beg; i < end; ++i) {
        g_rowptr[i] = off;
        g_widx[i]   = off;
        off += g_counts[i];
    }
    if (t == 1023) g_rowptr[NN] = sm[1023];
}

__global__ void k_scatter(const int* __restrict__ snd, const int* __restrict__ rcv,
                          const float* __restrict__ w) {
    int e4 = blockIdx.x * blockDim.x + threadIdx.x;
    if (e4 * 4 >= NE) return;
    int4   s4 = ((const int4*)snd)[e4];
    int4   r4 = ((const int4*)rcv)[e4];
    float4 w4 = ((const float4*)w)[e4];
    int p0 = atomicAdd(&g_widx[r4.x], 1);
    int p1 = atomicAdd(&g_widx[r4.y], 1);
    int p2 = atomicAdd(&g_widx[r4.z], 1);
    int p3 = atomicAdd(&g_widx[r4.w], 1);
    g_edges[p0] = make_int2(s4.x, __float_as_int(w4.x));
    g_edges[p1] = make_int2(s4.y, __float_as_int(w4.y));
    g_edges[p2] = make_int2(s4.z, __float_as_int(w4.z));
    g_edges[p3] = make_int2(s4.w, __float_as_int(w4.w));
}

// ---------------- GEMM1: h = relu(X[M,512] @ W1[512,64] + b1), FFMA2 ---------
__global__ __launch_bounds__(256) void k_gemm1(const float* __restrict__ A,
                                               const float* __restrict__ W,
                                               const float* __restrict__ bias,
                                               float* __restrict__ C, int M) {
    constexpr int BM = 256, BN = 64, BK = 16;
    __shared__ float As[BK][BM];
    __shared__ float Bs[BK][BN];
    const int tid = threadIdx.x;
    const int row0 = blockIdx.x * BM;
    const int tx = tid & 7;        // col group: cols tx*8 .. tx*8+7
    const int ty = tid >> 3;       // row group: rows ty*8 .. ty*8+7

    ull acc[8][4];
#pragma unroll
    for (int i = 0; i < 8; ++i)
#pragma unroll
        for (int j = 0; j < 4; ++j) acc[i][j] = 0ULL;

    const int arow = row0 + tid;
    const bool rowok = arow < M;
    const int br = tid >> 4, bc = (tid & 15) << 2;

    for (int k0 = 0; k0 < FIN; k0 += BK) {
#pragma unroll
        for (int c = 0; c < 4; ++c) {
            float4 v = make_float4(0.f, 0.f, 0.f, 0.f);
            if (rowok) v = *(const float4*)(A + (size_t)arow * FIN + k0 + c * 4);
            As[c * 4 + 0][tid] = v.x;
            As[c * 4 + 1][tid] = v.y;
            As[c * 4 + 2][tid] = v.z;
            As[c * 4 + 3][tid] = v.w;
        }
        *(float4*)&Bs[br][bc] = *(const float4*)(W + (size_t)(k0 + br) * BN + bc);
        __syncthreads();
#pragma unroll
        for (int kk = 0; kk < BK; ++kk) {
            float4 a0 = *(const float4*)&As[kk][ty * 8 + 0];
            float4 a1 = *(const float4*)&As[kk][ty * 8 + 4];
            float4 b0 = *(const float4*)&Bs[kk][tx * 8 + 0];
            float4 b1 = *(const float4*)&Bs[kk][tx * 8 + 4];
            ull bp[4] = { pack2(b0.x, b0.y), pack2(b0.z, b0.w),
                          pack2(b1.x, b1.y), pack2(b1.z, b1.w) };
            float av[8] = {a0.x, a0.y, a0.z, a0.w, a1.x, a1.y, a1.z, a1.w};
#pragma unroll
            for (int i = 0; i < 8; ++i) {
                ull ap = pack2(av[i], av[i]);
#pragma unroll
                for (int j = 0; j < 4; ++j) fma2(acc[i][j], ap, bp[j]);
            }
        }
        __syncthreads();
    }
#pragma unroll
    for (int i = 0; i < 8; ++i) {
        int r = row0 + ty * 8 + i;
        if (r < M) {
            float2 p0 = unpack2(acc[i][0]), p1 = unpack2(acc[i][1]);
            float2 p2 = unpack2(acc[i][2]), p3 = unpack2(acc[i][3]);
            float4 o0, o1;
            o0.x = fmaxf(p0.x + bias[tx * 8 + 0], 0.f);
            o0.y = fmaxf(p0.y + bias[tx * 8 + 1], 0.f);
            o0.z = fmaxf(p1.x + bias[tx * 8 + 2], 0.f);
            o0.w = fmaxf(p1.y + bias[tx * 8 + 3], 0.f);
            o1.x = fmaxf(p2.x + bias[tx * 8 + 4], 0.f);
            o1.y = fmaxf(p2.y + bias[tx * 8 + 5], 0.f);
            o1.z = fmaxf(p3.x + bias[tx * 8 + 6], 0.f);
            o1.w = fmaxf(p3.y + bias[tx * 8 + 7], 0.f);
            *(float4*)(C + (size_t)r * BN + tx * 8 + 0) = o0;
            *(float4*)(C + (size_t)r * BN + tx * 8 + 4) = o1;
        }
    }
}

// ------ GEMM2 + fused hop-0 gating: logits -> xA, out = sigmoid(.)·logits ----
__global__ __launch_bounds__(256) void k_gemm2_gate(const float* __restrict__ A,
                                                    const float* __restrict__ B,
                                                    const float* __restrict__ bias,
                                                    const float* __restrict__ Wg,
                                                    const float* __restrict__ bg,
                                                    float* __restrict__ X,
                                                    float* __restrict__ out, int M) {
    constexpr int BM = 128, BN = 64, BK = 16, K = HID;
    __shared__ float As[BK][BM + 4];
    __shared__ float Bs[BK][BN];
    const int tid = threadIdx.x;
    const int block_row = blockIdx.x * BM;
    const int tx = tid & 15;
    const int ty = tid >> 4;
    float acc[8][4];
#pragma unroll
    for (int i = 0; i < 8; ++i)
#pragma unroll
        for (int j = 0; j < 4; ++j) acc[i][j] = 0.f;

    const int ar = tid >> 2;
    const int ac = (tid & 3) << 2;
    const int br = tid >> 4;
    const int bc = (tid & 15) << 2;

    for (int k0 = 0; k0 < K; k0 += BK) {
#pragma unroll
        for (int i = 0; i < 2; ++i) {
            int row = block_row + ar + i * 64;
            float4 v = make_float4(0.f, 0.f, 0.f, 0.f);
            if (row < M) v = *(const float4*)(A + (size_t)row * K + k0 + ac);
            As[ac + 0][ar + i * 64] = v.x;
            As[ac + 1][ar + i * 64] = v.y;
            As[ac + 2][ar + i * 64] = v.z;
            As[ac + 3][ar + i * 64] = v.w;
        }
        *(float4*)&Bs[br][bc] = *(const float4*)(B + (size_t)(k0 + br) * BN + bc);
        __syncthreads();
#pragma unroll
        for (int kk = 0; kk < BK; ++kk) {
            float4 a0 = *(const float4*)&As[kk][ty * 8 + 0];
            float4 a1 = *(const float4*)&As[kk][ty * 8 + 4];
            float4 b0 = *(const float4*)&Bs[kk][tx * 4];
            float a[8] = {a0.x, a0.y, a0.z, a0.w, a1.x, a1.y, a1.z, a1.w};
            float b[4] = {b0.x, b0.y, b0.z, b0.w};
#pragma unroll
            for (int i = 0; i < 8; ++i)
#pragma unroll
                for (int j = 0; j < 4; ++j) acc[i][j] += a[i] * b[j];
        }
        __syncthreads();
    }
    // epilogue: add bias, compute row gate via 16-lane shfl reduction, write both
    float wgl[4];
#pragma unroll
    for (int j = 0; j < 4; ++j) wgl[j] = Wg[tx * 4 + j];
    float bgl = bg[0];
#pragma unroll
    for (int i = 0; i < 8; ++i) {
        float v0 = acc[i][0] + bias[tx * 4 + 0];
        float v1 = acc[i][1] + bias[tx * 4 + 1];
        float v2 = acc[i][2] + bias[tx * 4 + 2];
        float v3 = acc[i][3] + bias[tx * 4 + 3];
        float part = v0 * wgl[0] + v1 * wgl[1] + v2 * wgl[2] + v3 * wgl[3];
#pragma unroll
        for (int o = 8; o; o >>= 1) part += __shfl_xor_sync(0xffffffffu, part, o);
        float gsc = 1.f / (1.f + __expf(-(part + bgl)));
        int row = block_row + ty * 8 + i;
        if (row < M) {
            float4 v = make_float4(v0, v1, v2, v3);
            *(float4*)(X + (size_t)row * BN + tx * 4) = v;
            float4 o4 = make_float4(gsc * v0, gsc * v1, gsc * v2, gsc * v3);
            *(float4*)(out + (size_t)row * BN + tx * 4) = o4;
        }
    }
}

// ---------------- SpMM (gather CSR) + fused gated accumulation ---------------
__global__ __launch_bounds__(256) void k_spmm_gate(int ab, int store_y,
                                                   const float* __restrict__ Wg,
                                                   const float* __restrict__ bg,
                                                   float* __restrict__ out) {
    int gw = (blockIdx.x * blockDim.x + threadIdx.x) >> 5;  // node (warp per node)
    int lane = threadIdx.x & 31;
    if (gw >= NN) return;
    const float2* __restrict__ x2 = ab ? (const float2*)g_xB : (const float2*)g_xA;
    float2* __restrict__ y2       = ab ? (float2*)g_xA       : (float2*)g_xB;

    int beg = g_rowptr[gw];
    int end = g_rowptr[gw + 1];
    float2 acc = make_float2(0.f, 0.f);

    int e = beg;
    for (; e + 4 <= end; e += 4) {
        int2 e0 = g_edges[e + 0];
        int2 e1 = g_edges[e + 1];
        int2 e2 = g_edges[e + 2];
        int2 e3 = g_edges[e + 3];
        float2 v0 = x2[(size_t)e0.x * 32 + lane];
        float2 v1 = x2[(size_t)e1.x * 32 + lane];
        float2 v2 = x2[(size_t)e2.x * 32 + lane];
        float2 v3 = x2[(size_t)e3.x * 32 + lane];
        float w0 = __int_as_float(e0.y), w1 = __int_as_float(e1.y);
        float w2 = __int_as_float(e2.y), w3 = __int_as_float(e3.y);
        acc.x += w0 * v0.x; acc.y += w0 * v0.y;
        acc.x += w1 * v1.x; acc.y += w1 * v1.y;
        acc.x += w2 * v2.x; acc.y += w2 * v2.y;
        acc.x += w3 * v3.x; acc.y += w3 * v3.y;
    }
    for (; e < end; ++e) {
        int2 ep = g_edges[e];
        float w = __int_as_float(ep.y);
        float2 v = x2[(size_t)ep.x * 32 + lane];
        acc.x += w * v.x; acc.y += w * v.y;
    }

    if (store_y) y2[(size_t)gw * 32 + lane] = acc;

    // fused gated-sum accumulation
    float part = acc.x * Wg[2 * lane] + acc.y * Wg[2 * lane + 1];
#pragma unroll
    for (int o = 16; o; o >>= 1) part += __shfl_xor_sync(0xffffffffu, part, o);
    float gsc = 1.f / (1.f + __expf(-(part + bg[0])));
    float2* o2 = (float2*)out;
    float2 cur = o2[(size_t)gw * 32 + lane];
    cur.x += gsc * acc.x;
    cur.y += gsc * acc.y;
    o2[(size_t)gw * 32 + lane] = cur;
}

// ---------------- launch -----------------------------------------------------
extern "C" void kernel_launch(void* const* d_in, const int* in_sizes, int n_in,
                              void* d_out, int out_size) {
    const float* X   = (const float*)d_in[0];
    const float* ew  = (const float*)d_in[1];
    const float* W1  = (const float*)d_in[2];
    const float* b1  = (const float*)d_in[3];
    const float* W2  = (const float*)d_in[4];
    const float* b2  = (const float*)d_in[5];
    const float* Wg  = (const float*)d_in[6];
    const float* bg  = (const float*)d_in[7];
    const int*   snd = (const int*)d_in[8];
    const int*   rcv = (const int*)d_in[9];
    float* out = (float*)d_out;

    void* p;
    cudaGetSymbolAddress(&p, g_h);  float* hptr = (float*)p;
    cudaGetSymbolAddress(&p, g_xA); float* xA   = (float*)p;

    // CSR build (once per launch)
    k_zero_counts<<<(NN + 255) / 256, 256>>>();
    const int E4B = (NE / 4 + 255) / 256;
    k_hist<<<E4B, 256>>>(rcv);
    k_scan<<<1, 1024>>>();
    k_scatter<<<E4B, 256>>>(snd, rcv, ew);

    // MLP: h = relu(X@W1+b1) via FFMA2; logits = h@W2+b2 -> xA, fused hop-0 gate -> out
    k_gemm1<<<(NN + 255) / 256, 256>>>(X, W1, b1, hptr, NN);
    k_gemm2_gate<<<(NN + 127) / 128, 256>>>(hptr, W2, b2, Wg, bg, xA, out, NN);

    // 20 propagations, ping-pong, gating fused; last hop skips y-store
    const int SPB = (NN + 7) / 8;   // 8 warps/block
    for (int k = 0; k < KHOPS; ++k)
        k_spmm_gate<<<SPB, 256>>>(k & 1, (k < KHOPS - 1) ? 1 : 0, Wg, bg, out);
}